// round 16
// baseline (speedup 1.0000x reference)
#include <cuda_runtime.h>
#include <cuda_fp16.h>
#include <cstdint>
#include <cstddef>

// ---------------------------------------------------------------------------
// GATEncoder: GATConv(2000->4x512, mean heads) -> BN -> ELU -> GATConv(512->30)
// N=50000, F=2000, H=4, C=512, LAT=30, E=800000 (+N self loops)
// R16: BN stats fused into agg1 epilogue (k_bnstats deleted; spread atomics
//      rate-checked vs L2 ceiling) + agg1 phase-C edge loop unrolled x2 for
//      MLP. Everything else identical to the 2486us R15.
// ---------------------------------------------------------------------------

#define NMAX 50000
#define EMAX 800000
#define ETMAX (EMAX + NMAX)

#define GEMM_STAGES 4
#define ROW_BYTES 80                       // 32 halfs (64B) + 16B pad: LDSM conflict-free
#define OP_TILE (128 * ROW_BYTES)          // 10240 B per operand per stage
#define STAGE_BYTES (2 * OP_TILE)          // 20480
#define SMEM_GEMM (GEMM_STAGES * STAGE_BYTES)   // 81920

// ---- device scratch (static; no runtime allocation allowed) ----
__device__ __half   g_H1h[(size_t)NMAX * 2048];   // x @ W1 in fp16
__device__ __half   g_Ah[(size_t)NMAX * 2000];    // x in fp16
__device__ __half   g_W1h[(size_t)2048 * 2000];   // W1^T in fp16 ([n][k])
__device__ float    g_out1[(size_t)NMAX * 512];   // layer-1 aggregate
__device__ float    g_H2[(size_t)NMAX * 30];      // ELU(BN(out1)) @ W2
__device__ float    g_asrc1[NMAX * 4];
__device__ float    g_adst1[NMAX * 4];
__device__ float    g_asrc2[NMAX];
__device__ float    g_adst2[NMAX];
__device__ float    g_stats[1024];                // [0:512) sum, [512:1024) sumsq
// CSR by destination
__device__ int      g_deg[NMAX];
__device__ int      g_rowptr[NMAX + 1];
__device__ int      g_woff[NMAX];
__device__ int      g_csr_src[ETMAX];

// ---- helpers ----
__device__ __forceinline__ uint32_t h2u(__half2 h) {
    __half2_raw r = *reinterpret_cast<__half2_raw*>(&h);
    return (uint32_t)r.x | ((uint32_t)r.y << 16);
}
__device__ __forceinline__ float2 u2f2(uint32_t u) {
    __half2_raw r; r.x = (unsigned short)(u & 0xFFFFu); r.y = (unsigned short)(u >> 16);
    __half2 h = *reinterpret_cast<__half2*>(&r);
    return __half22float2(h);
}
__device__ __forceinline__ float lrelu(float v) { return v > 0.f ? v : 0.2f * v; }

__device__ __forceinline__ void cp16(uint32_t saddr, const void* gptr, bool pred) {
    int sz = pred ? 16 : 0;   // sz=0 -> 16 bytes zero-filled (src-size form)
    asm volatile("cp.async.cg.shared.global [%0], [%1], 16, %2;\n"
                 :: "r"(saddr), "l"(gptr), "r"(sz));
}
__device__ __forceinline__ void cp_commit() {
    asm volatile("cp.async.commit_group;\n" ::: "memory");
}
__device__ __forceinline__ void cp_waitg() {
    asm volatile("cp.async.wait_group %0;\n" :: "n"(GEMM_STAGES - 2) : "memory");
}
__device__ __forceinline__ void ldsm4(uint32_t* r, uint32_t addr) {
    asm volatile("ldmatrix.sync.aligned.m8n8.x4.shared.b16 {%0,%1,%2,%3}, [%4];"
                 : "=r"(r[0]), "=r"(r[1]), "=r"(r[2]), "=r"(r[3]) : "r"(addr));
}

// ---------------------------------------------------------------------------
// init: zero CSR degree + BN stats + attention partial-dot accumulators
// ---------------------------------------------------------------------------
__global__ void k_init(int Nn) {
    int total = Nn * 4;
    for (int i = blockIdx.x * blockDim.x + threadIdx.x; i < total;
         i += gridDim.x * blockDim.x) {
        g_asrc1[i] = 0.f;
        g_adst1[i] = 0.f;
        if (i < Nn) g_deg[i] = 0;
        if (i < 1024) g_stats[i] = 0.f;
    }
}

// ---------------------------------------------------------------------------
// conversions: x -> fp16 ; W1 -> fp16 transposed [n][k]
// ---------------------------------------------------------------------------
__global__ void k_cvtA(const float* __restrict__ x, size_t n8) {
    const float4* src = (const float4*)x;
    uint4* dst = (uint4*)g_Ah;
    for (size_t i = (size_t)blockIdx.x * blockDim.x + threadIdx.x; i < n8;
         i += (size_t)gridDim.x * blockDim.x) {
        float4 v0 = __ldg(src + 2 * i);
        float4 v1 = __ldg(src + 2 * i + 1);
        uint4 o;
        o.x = h2u(__floats2half2_rn(v0.x, v0.y));
        o.y = h2u(__floats2half2_rn(v0.z, v0.w));
        o.z = h2u(__floats2half2_rn(v1.x, v1.y));
        o.w = h2u(__floats2half2_rn(v1.z, v1.w));
        dst[i] = o;
    }
}

__global__ void k_cvtBT(const float* __restrict__ W1) {
    __shared__ float t[32][33];
    int n0 = blockIdx.x * 32, k0 = blockIdx.y * 32;
    int tx = threadIdx.x, ty = threadIdx.y;   // 32 x 8
#pragma unroll
    for (int i = 0; i < 32; i += 8) {
        int k = k0 + ty + i;
        t[ty + i][tx] = (k < 2000) ? W1[(size_t)k * 2048 + n0 + tx] : 0.f;
    }
    __syncthreads();
#pragma unroll
    for (int i = 0; i < 32; i += 8) {
        int k = k0 + tx;
        if (k < 2000)
            g_W1h[(size_t)(n0 + ty + i) * 2000 + k] = __float2half_rn(t[tx][ty + i]);
    }
}

// ---------------------------------------------------------------------------
// CSR build: degree count -> exclusive scan -> scatter (src indices)
// ---------------------------------------------------------------------------
__global__ void k_deg(const int* __restrict__ ei, int E, int Nn) {
    int e = blockIdx.x * blockDim.x + threadIdx.x;
    if (e >= E + Nn) return;
    int d = (e < E) ? ei[E + e] : e - E;
    atomicAdd(&g_deg[d], 1);
}

__global__ void k_scan(int Nn) {
    __shared__ int wsum[32];
    __shared__ int carry_s;
    int tid = threadIdx.x;
    if (tid == 0) carry_s = 0;
    __syncthreads();
    int iters = (Nn + 1023) / 1024;
    for (int it = 0; it < iters; it++) {
        int i = it * 1024 + tid;
        int v = (i < Nn) ? g_deg[i] : 0;
        int x = v;
#pragma unroll
        for (int o = 1; o < 32; o <<= 1) {
            int y = __shfl_up_sync(0xffffffffu, x, o);
            if ((tid & 31) >= o) x += y;
        }
        if ((tid & 31) == 31) wsum[tid >> 5] = x;
        __syncthreads();
        if (tid < 32) {
            int w = wsum[tid];
#pragma unroll
            for (int o = 1; o < 32; o <<= 1) {
                int y = __shfl_up_sync(0xffffffffu, w, o);
                if (tid >= o) w += y;
            }
            wsum[tid] = w;
        }
        __syncthreads();
        int warp = tid >> 5;
        int incl = x + (warp ? wsum[warp - 1] : 0);
        int excl = incl - v;
        int c = carry_s;
        if (i < Nn) { g_rowptr[i] = c + excl; g_woff[i] = c + excl; }
        __syncthreads();
        if (tid == 1023) carry_s = c + incl;
        __syncthreads();
    }
    if (tid == 0) g_rowptr[Nn] = carry_s;
}

__global__ void k_scatter(const int* __restrict__ ei, int E, int Nn) {
    int e = blockIdx.x * blockDim.x + threadIdx.x;
    if (e >= E + Nn) return;
    int s, d;
    if (e < E) { s = ei[e]; d = ei[E + e]; } else { s = d = e - E; }
    int pos = atomicAdd(&g_woff[d], 1);
    g_csr_src[pos] = s;
}

// ---------------------------------------------------------------------------
// GEMM1 + fused attention dots: g_H1h = Ah @ W1h^T (fp16 mma, f32 accum,
// fp16 out). Epilogue computes per-(row,head) partial dots -> spread atomics.
// ---------------------------------------------------------------------------
__global__ __launch_bounds__(256, 2)
void k_gemm1h(const float* __restrict__ att_src, const float* __restrict__ att_dst,
              int M) {
    extern __shared__ char smem[];
    const uint32_t sb = (uint32_t)__cvta_generic_to_shared(smem);
    const __half* A = g_Ah;
    const __half* B = g_W1h;

    const int tid  = threadIdx.x;
    const int lane = tid & 31, warp = tid >> 5;
    const int gid  = lane >> 2, tig = lane & 3;
    const int wm   = warp >> 1, wn = warp & 1;
    const int rowBase = blockIdx.y * 128;
    const int colBase = blockIdx.x * 128;
    const int KITERS = 63;   // ceil(2000/32); tail chunks zero-filled by cp.async

    const int mrow = (lane & 7) + ((lane >> 3) & 1) * 8;
    const int koff = ((lane >> 4) & 1) * 16;

    float acc[2][8][4];
#pragma unroll
    for (int i = 0; i < 2; i++)
#pragma unroll
        for (int j = 0; j < 8; j++)
#pragma unroll
            for (int k = 0; k < 4; k++) acc[i][j][k] = 0.f;

    auto load_tile = [&](int st, int k0) {
        uint32_t aBase = sb + st * STAGE_BYTES;
        uint32_t bBase = aBase + OP_TILE;
#pragma unroll
        for (int i = 0; i < 2; i++) {
            int idx = tid + i * 256;
            int r = idx >> 2, j = idx & 3;
            int gr = rowBase + r;
            bool p = (gr < M) && (k0 + j * 8 < 2000);
            cp16(aBase + r * ROW_BYTES + j * 16, A + (size_t)gr * 2000 + k0 + j * 8, p);
        }
#pragma unroll
        for (int i = 0; i < 2; i++) {
            int idx = tid + i * 256;
            int r = idx >> 2, j = idx & 3;
            bool p = (k0 + j * 8 < 2000);
            cp16(bBase + r * ROW_BYTES + j * 16,
                 B + (size_t)(colBase + r) * 2000 + k0 + j * 8, p);
        }
    };

#pragma unroll
    for (int s = 0; s < GEMM_STAGES - 1; s++) {
        load_tile(s, s * 32);
        cp_commit();
    }

    for (int it = 0; it < KITERS; it++) {
        cp_waitg();
        __syncthreads();
        int st = it & (GEMM_STAGES - 1);
        uint32_t aBase = sb + st * STAGE_BYTES;
        uint32_t bBase = aBase + OP_TILE;
#pragma unroll
        for (int ks = 0; ks < 2; ks++) {
            uint32_t a[2][4], bf[4][4];
#pragma unroll
            for (int tm = 0; tm < 2; tm++) {
                uint32_t addr = aBase + (wm * 32 + tm * 16 + mrow) * ROW_BYTES
                              + ks * 32 + koff;
                ldsm4(a[tm], addr);
            }
#pragma unroll
            for (int tp = 0; tp < 4; tp++) {
                uint32_t addr = bBase + (wn * 64 + tp * 16 + mrow) * ROW_BYTES
                              + ks * 32 + koff;
                ldsm4(bf[tp], addr);
            }
#pragma unroll
            for (int tm = 0; tm < 2; tm++)
#pragma unroll
                for (int tp = 0; tp < 4; tp++) {
                    asm volatile(
                        "mma.sync.aligned.m16n8k16.row.col.f32.f16.f16.f32 "
                        "{%0,%1,%2,%3},{%4,%5,%6,%7},{%8,%9},{%0,%1,%2,%3};\n"
                        : "+f"(acc[tm][tp * 2][0]), "+f"(acc[tm][tp * 2][1]),
                          "+f"(acc[tm][tp * 2][2]), "+f"(acc[tm][tp * 2][3])
                        : "r"(a[tm][0]), "r"(a[tm][1]), "r"(a[tm][2]), "r"(a[tm][3]),
                          "r"(bf[tp][0]), "r"(bf[tp][2]));
                    asm volatile(
                        "mma.sync.aligned.m16n8k16.row.col.f32.f16.f16.f32 "
                        "{%0,%1,%2,%3},{%4,%5,%6,%7},{%8,%9},{%0,%1,%2,%3};\n"
                        : "+f"(acc[tm][tp * 2 + 1][0]), "+f"(acc[tm][tp * 2 + 1][1]),
                          "+f"(acc[tm][tp * 2 + 1][2]), "+f"(acc[tm][tp * 2 + 1][3])
                        : "r"(a[tm][0]), "r"(a[tm][1]), "r"(a[tm][2]), "r"(a[tm][3]),
                          "r"(bf[tp][1]), "r"(bf[tp][3]));
                }
        }
        int nit = it + GEMM_STAGES - 1;
        if (nit < KITERS) load_tile(nit & (GEMM_STAGES - 1), nit * 32);
        cp_commit();
    }

    // ---- epilogue: fp16 H1 store + fused attention partial dots ----
    const int hIdx = colBase >> 9;                      // single head per CTA
    const int cgBase = (colBase & 511) + wn * 64 + tig * 2;
    const float* asv = att_src + hIdx * 512;
    const float* adv = att_dst + hIdx * 512;

    float psrc[4] = {0.f, 0.f, 0.f, 0.f};               // [tm*2 + half]
    float pdst[4] = {0.f, 0.f, 0.f, 0.f};

#pragma unroll
    for (int tm = 0; tm < 2; tm++) {
        int r0 = rowBase + wm * 32 + tm * 16 + gid;
#pragma unroll
        for (int tn = 0; tn < 8; tn++) {
            int c = colBase + wn * 64 + tn * 8 + tig * 2;
            uint32_t p01 = h2u(__floats2half2_rn(acc[tm][tn][0], acc[tm][tn][1]));
            uint32_t p23 = h2u(__floats2half2_rn(acc[tm][tn][2], acc[tm][tn][3]));
            if (r0 < M)
                *(uint32_t*)(g_H1h + (size_t)r0 * 2048 + c) = p01;
            if (r0 + 8 < M)
                *(uint32_t*)(g_H1h + (size_t)(r0 + 8) * 2048 + c) = p23;

            float2 av = __ldg((const float2*)(asv + cgBase + tn * 8));
            float2 dv = __ldg((const float2*)(adv + cgBase + tn * 8));
            psrc[tm * 2 + 0] += acc[tm][tn][0] * av.x + acc[tm][tn][1] * av.y;
            psrc[tm * 2 + 1] += acc[tm][tn][2] * av.x + acc[tm][tn][3] * av.y;
            pdst[tm * 2 + 0] += acc[tm][tn][0] * dv.x + acc[tm][tn][1] * dv.y;
            pdst[tm * 2 + 1] += acc[tm][tn][2] * dv.x + acc[tm][tn][3] * dv.y;
        }
    }
#pragma unroll
    for (int tm = 0; tm < 2; tm++)
#pragma unroll
        for (int half = 0; half < 2; half++) {
            int row = rowBase + wm * 32 + tm * 16 + half * 8 + gid;
            if (row < M) {
                atomicAdd(g_asrc1 + row * 4 + hIdx, psrc[tm * 2 + half]);
                atomicAdd(g_adst1 + row * 4 + hIdx, pdst[tm * 2 + half]);
            }
        }
}

// ---------------------------------------------------------------------------
// fused layer-1 softmax + aggregation + BN stats: one block per destination.
// Phase-C unrolled x2 for MLP; stats accumulated via spread atomics.
// ---------------------------------------------------------------------------
__global__ __launch_bounds__(256)
void k_agg1(int Nn) {
    const int d = blockIdx.x;
    const int tid = threadIdx.x, lane = tid & 31, warp = tid >> 5;
    const int beg = g_rowptr[d], end = g_rowptr[d + 1];

    __shared__ float4 rwarp[8];
    __shared__ float4 rbc;
    __shared__ int    ssrc[256];
    __shared__ float4 sal[256];

    float4 ad = *(const float4*)(g_adst1 + (size_t)d * 4);
    const float NEGINF = __int_as_float(0xff800000);

    float4 mx = make_float4(NEGINF, NEGINF, NEGINF, NEGINF);
    for (int j = beg + tid; j < end; j += 256) {
        int s = g_csr_src[j];
        float4 as = *(const float4*)(g_asrc1 + (size_t)s * 4);
        mx.x = fmaxf(mx.x, lrelu(as.x + ad.x));
        mx.y = fmaxf(mx.y, lrelu(as.y + ad.y));
        mx.z = fmaxf(mx.z, lrelu(as.z + ad.z));
        mx.w = fmaxf(mx.w, lrelu(as.w + ad.w));
    }
#pragma unroll
    for (int o = 16; o; o >>= 1) {
        mx.x = fmaxf(mx.x, __shfl_down_sync(0xffffffffu, mx.x, o));
        mx.y = fmaxf(mx.y, __shfl_down_sync(0xffffffffu, mx.y, o));
        mx.z = fmaxf(mx.z, __shfl_down_sync(0xffffffffu, mx.z, o));
        mx.w = fmaxf(mx.w, __shfl_down_sync(0xffffffffu, mx.w, o));
    }
    if (lane == 0) rwarp[warp] = mx;
    __syncthreads();
    if (tid == 0) {
        float4 m = rwarp[0];
#pragma unroll
        for (int w = 1; w < 8; w++) {
            m.x = fmaxf(m.x, rwarp[w].x); m.y = fmaxf(m.y, rwarp[w].y);
            m.z = fmaxf(m.z, rwarp[w].z); m.w = fmaxf(m.w, rwarp[w].w);
        }
        rbc = m;
    }
    __syncthreads();
    mx = rbc;

    float4 sm = make_float4(0.f, 0.f, 0.f, 0.f);
    for (int j = beg + tid; j < end; j += 256) {
        int s = g_csr_src[j];
        float4 as = *(const float4*)(g_asrc1 + (size_t)s * 4);
        sm.x += expf(lrelu(as.x + ad.x) - mx.x);
        sm.y += expf(lrelu(as.y + ad.y) - mx.y);
        sm.z += expf(lrelu(as.z + ad.z) - mx.z);
        sm.w += expf(lrelu(as.w + ad.w) - mx.w);
    }
#pragma unroll
    for (int o = 16; o; o >>= 1) {
        sm.x += __shfl_down_sync(0xffffffffu, sm.x, o);
        sm.y += __shfl_down_sync(0xffffffffu, sm.y, o);
        sm.z += __shfl_down_sync(0xffffffffu, sm.z, o);
        sm.w += __shfl_down_sync(0xffffffffu, sm.w, o);
    }
    if (lane == 0) rwarp[warp] = sm;
    __syncthreads();
    if (tid == 0) {
        float4 t = rwarp[0];
#pragma unroll
        for (int w = 1; w < 8; w++) {
            t.x += rwarp[w].x; t.y += rwarp[w].y; t.z += rwarp[w].z; t.w += rwarp[w].w;
        }
        rbc = t;
    }
    __syncthreads();
    sm = rbc;
    float4 inv;
    inv.x = 0.25f / (sm.x + 1e-16f);
    inv.y = 0.25f / (sm.y + 1e-16f);
    inv.z = 0.25f / (sm.z + 1e-16f);
    inv.w = 0.25f / (sm.w + 1e-16f);

    float2 acc = make_float2(0.f, 0.f);
    for (int c0 = beg; c0 < end; c0 += 256) {
        int cnt = min(end - c0, 256);
        __syncthreads();
        if (tid < cnt) {
            int s = g_csr_src[c0 + tid];
            float4 as = *(const float4*)(g_asrc1 + (size_t)s * 4);
            float4 al;
            al.x = expf(lrelu(as.x + ad.x) - mx.x) * inv.x;
            al.y = expf(lrelu(as.y + ad.y) - mx.y) * inv.y;
            al.z = expf(lrelu(as.z + ad.z) - mx.z) * inv.z;
            al.w = expf(lrelu(as.w + ad.w) - mx.w) * inv.w;
            ssrc[tid] = s;
            sal[tid] = al;
        }
        __syncthreads();
        int jj = 0;
        for (; jj + 2 <= cnt; jj += 2) {                 // x2 unroll: 8 loads in flight
            const __half* h0 = g_H1h + (size_t)ssrc[jj] * 2048 + 2 * tid;
            const __half* h1 = g_H1h + (size_t)ssrc[jj + 1] * 2048 + 2 * tid;
            uint32_t a0 = __ldg((const uint32_t*)(h0));
            uint32_t a1 = __ldg((const uint32_t*)(h0 + 512));
            uint32_t a2 = __ldg((const uint32_t*)(h0 + 1024));
            uint32_t a3 = __ldg((const uint32_t*)(h0 + 1536));
            uint32_t b0 = __ldg((const uint32_t*)(h1));
            uint32_t b1 = __ldg((const uint32_t*)(h1 + 512));
            uint32_t b2 = __ldg((const uint32_t*)(h1 + 1024));
            uint32_t b3 = __ldg((const uint32_t*)(h1 + 1536));
            float4 al0 = sal[jj], al1 = sal[jj + 1];
            float2 v0 = u2f2(a0), v1 = u2f2(a1), v2 = u2f2(a2), v3 = u2f2(a3);
            acc.x += al0.x * v0.x + al0.y * v1.x + al0.z * v2.x + al0.w * v3.x;
            acc.y += al0.x * v0.y + al0.y * v1.y + al0.z * v2.y + al0.w * v3.y;
            float2 w0 = u2f2(b0), w1 = u2f2(b1), w2 = u2f2(b2), w3 = u2f2(b3);
            acc.x += al1.x * w0.x + al1.y * w1.x + al1.z * w2.x + al1.w * w3.x;
            acc.y += al1.x * w0.y + al1.y * w1.y + al1.z * w2.y + al1.w * w3.y;
        }
        if (jj < cnt) {
            const __half* h = g_H1h + (size_t)ssrc[jj] * 2048 + 2 * tid;
            float4 al = sal[jj];
            float2 v0 = u2f2(__ldg((const uint32_t*)(h)));
            float2 v1 = u2f2(__ldg((const uint32_t*)(h + 512)));
            float2 v2 = u2f2(__ldg((const uint32_t*)(h + 1024)));
            float2 v3 = u2f2(__ldg((const uint32_t*)(h + 1536)));
            acc.x += al.x * v0.x + al.y * v1.x + al.z * v2.x + al.w * v3.x;
            acc.y += al.x * v0.y + al.y * v1.y + al.z * v2.y + al.w * v3.y;
        }
    }
    *(float2*)(g_out1 + (size_t)d * 512 + 2 * tid) = acc;

    // fused BN stats: each thread owns channels 2t, 2t+1
    atomicAdd(&g_stats[2 * tid],       acc.x);
    atomicAdd(&g_stats[2 * tid + 1],   acc.y);
    atomicAdd(&g_stats[512 + 2 * tid],     acc.x * acc.x);
    atomicAdd(&g_stats[512 + 2 * tid + 1], acc.y * acc.y);
}

// ---------------------------------------------------------------------------
// layer-2 prep with fused BN+ELU: H2 = ELU(BN(out1)) @ W2 (one warp per row)
// ---------------------------------------------------------------------------
__global__ void k_l2prep(const float* __restrict__ W2, const float* __restrict__ as2,
                         const float* __restrict__ ad2, const float* __restrict__ gamma,
                         const float* __restrict__ beta, int Nn, float invN) {
    int gw = (int)(((size_t)blockIdx.x * blockDim.x + threadIdx.x) >> 5);
    int lane = threadIdx.x & 31;
    if (gw >= Nn) return;
    const float* h = g_out1 + (size_t)gw * 512;
    float acc = 0.f;
    for (int kb = 0; kb < 16; kb++) {
        int c = kb * 32 + lane;
        float mu = __ldg(g_stats + c) * invN;
        float var = __ldg(g_stats + 512 + c) * invN - mu * mu;
        float scale = rsqrtf(var + 1e-5f) * __ldg(gamma + c);
        float shift = __ldg(beta + c) - mu * scale;
        float xv = h[c] * scale + shift;
        float hv = xv > 0.f ? xv : expm1f(xv);
#pragma unroll
        for (int j = 0; j < 32; j++) {
            float hk = __shfl_sync(0xffffffffu, hv, j);
            float w = (lane < 30) ? __ldg(W2 + (size_t)(kb * 32 + j) * 30 + lane) : 0.f;
            acc = fmaf(hk, w, acc);
        }
    }
    float sa = (lane < 30) ? acc * __ldg(as2 + lane) : 0.f;
    float sd = (lane < 30) ? acc * __ldg(ad2 + lane) : 0.f;
#pragma unroll
    for (int off = 16; off; off >>= 1) {
        sa += __shfl_down_sync(0xffffffffu, sa, off);
        sd += __shfl_down_sync(0xffffffffu, sd, off);
    }
    if (lane < 30) g_H2[(size_t)gw * 30 + lane] = acc;
    if (lane == 0) { g_asrc2[gw] = sa; g_adst2[gw] = sd; }
}

// ---------------------------------------------------------------------------
// fused layer-2 softmax + aggregation: one warp per destination.
// ---------------------------------------------------------------------------
__global__ __launch_bounds__(256)
void k_l2agg(const float* __restrict__ b2, float* __restrict__ out, int Nn) {
    int gw = (int)(((size_t)blockIdx.x * blockDim.x + threadIdx.x) >> 5);
    int lane = threadIdx.x & 31;
    if (gw >= Nn) return;
    const int d = gw;
    const int beg = g_rowptr[d], end = g_rowptr[d + 1];
    const float adv = g_adst2[d];
    const float NEGINF = __int_as_float(0xff800000);

    float mx = NEGINF;
    for (int j = beg + lane; j < end; j += 32)
        mx = fmaxf(mx, lrelu(__ldg(g_asrc2 + g_csr_src[j]) + adv));
#pragma unroll
    for (int o = 16; o; o >>= 1)
        mx = fmaxf(mx, __shfl_xor_sync(0xffffffffu, mx, o));

    float sm = 0.f;
    for (int j = beg + lane; j < end; j += 32)
        sm += expf(lrelu(__ldg(g_asrc2 + g_csr_src[j]) + adv) - mx);
#pragma unroll
    for (int o = 16; o; o >>= 1)
        sm += __shfl_xor_sync(0xffffffffu, sm, o);
    float inv = 1.f / (sm + 1e-16f);

    float acc = 0.f;
    for (int j = beg; j < end; j++) {
        int s = g_csr_src[j];
        float al = expf(lrelu(__ldg(g_asrc2 + s) + adv) - mx) * inv;
        if (lane < 30) acc = fmaf(al, __ldg(g_H2 + (size_t)s * 30 + lane), acc);
    }
    if (lane < 30) out[(size_t)d * 30 + lane] = acc + __ldg(b2 + lane);
}

// ---------------------------------------------------------------------------
// launch: fork CSR branch (deg/scan/scatter) parallel to cvt+GEMM branch
// ---------------------------------------------------------------------------
extern "C" void kernel_launch(void* const* d_in, const int* in_sizes, int n_in,
                              void* d_out, int out_size) {
    const float* x       = (const float*)d_in[0];
    const int*   ei      = (const int*)d_in[1];
    const float* W1      = (const float*)d_in[2];
    const float* attsrc1 = (const float*)d_in[3];
    const float* attdst1 = (const float*)d_in[4];
    // d_in[5] = b1: BN-invariant, skipped
    const float* gamma   = (const float*)d_in[6];
    const float* beta    = (const float*)d_in[7];
    const float* W2      = (const float*)d_in[8];
    const float* attsrc2 = (const float*)d_in[9];
    const float* attdst2 = (const float*)d_in[10];
    const float* b2      = (const float*)d_in[11];
    float* out = (float*)d_out;

    int Nn = in_sizes[0] / 2000;
    int E  = in_sizes[1] / 2;
    int Etot = E + Nn;
    int eb = (Etot + 255) / 256;

    cudaFuncSetAttribute(k_gemm1h, cudaFuncAttributeMaxDynamicSharedMemorySize, SMEM_GEMM);

    cudaStream_t s2;
    cudaEvent_t evFork, evJoin;
    cudaStreamCreateWithFlags(&s2, cudaStreamNonBlocking);
    cudaEventCreateWithFlags(&evFork, cudaEventDisableTiming);
    cudaEventCreateWithFlags(&evJoin, cudaEventDisableTiming);

    k_init<<<512, 256>>>(Nn);

    // fork: CSR branch on s2
    cudaEventRecord(evFork, 0);
    cudaStreamWaitEvent(s2, evFork, 0);
    k_deg<<<eb, 256, 0, s2>>>(ei, E, Nn);
    k_scan<<<1, 1024, 0, s2>>>(Nn);
    k_scatter<<<eb, 256, 0, s2>>>(ei, E, Nn);
    cudaEventRecord(evJoin, s2);

    // main branch: conversions + GEMM(+att dots)
    k_cvtA<<<2048, 256>>>(x, (size_t)Nn * 2000 / 8);
    k_cvtBT<<<dim3(64, 63), dim3(32, 8)>>>(W1);
    dim3 g1(16, (Nn + 127) / 128);
    k_gemm1h<<<g1, 256, SMEM_GEMM>>>(attsrc1, attdst1, Nn);

    // join: agg1 needs CSR + attention scalars
    cudaStreamWaitEvent(0, evJoin, 0);
    k_agg1<<<Nn, 256>>>(Nn);

    k_l2prep<<<(int)(((size_t)Nn * 32 + 255) / 256), 256>>>(
        W2, attsrc2, attdst2, gamma, beta, Nn, 1.f / (float)Nn);

    k_l2agg<<<(int)(((size_t)Nn * 32 + 255) / 256), 256>>>(b2, out, Nn);
}

// round 17
// speedup vs baseline: 1.1796x; 1.1796x over previous
#include <cuda_runtime.h>
#include <cuda_fp16.h>
#include <cstdint>
#include <cstddef>

// ---------------------------------------------------------------------------
// GATEncoder: GATConv(2000->4x512, mean heads) -> BN -> ELU -> GATConv(512->30)
// N=50000, F=2000, H=4, C=512, LAT=30, E=800000 (+N self loops)
// R17: recover from R16 regression (51M atomics on 1024 addrs = per-address
//      L2-ALU serialization). BN stats fused into agg1 again but scattered
//      into a hashed partial buffer g_pstats[512][1024] (~49 atomics/addr,
//      k_deg regime) + tiny reduction. Phase-C unroll reverted (confounded).
//      Everything else identical to the 2486us R15.
// ---------------------------------------------------------------------------

#define NMAX 50000
#define EMAX 800000
#define ETMAX (EMAX + NMAX)

#define GEMM_STAGES 4
#define ROW_BYTES 80                       // 32 halfs (64B) + 16B pad: LDSM conflict-free
#define OP_TILE (128 * ROW_BYTES)          // 10240 B per operand per stage
#define STAGE_BYTES (2 * OP_TILE)          // 20480
#define SMEM_GEMM (GEMM_STAGES * STAGE_BYTES)   // 81920

#define PSLOTS 512

// ---- device scratch (static; no runtime allocation allowed) ----
__device__ __half   g_H1h[(size_t)NMAX * 2048];   // x @ W1 in fp16
__device__ __half   g_Ah[(size_t)NMAX * 2000];    // x in fp16
__device__ __half   g_W1h[(size_t)2048 * 2000];   // W1^T in fp16 ([n][k])
__device__ float    g_out1[(size_t)NMAX * 512];   // layer-1 aggregate
__device__ float    g_H2[(size_t)NMAX * 30];      // ELU(BN(out1)) @ W2
__device__ float    g_asrc1[NMAX * 4];
__device__ float    g_adst1[NMAX * 4];
__device__ float    g_asrc2[NMAX];
__device__ float    g_adst2[NMAX];
__device__ float    g_pstats[PSLOTS * 1024];      // hashed partial BN stats (2 MB)
__device__ float    g_stats[1024];                // [0:512) sum, [512:1024) sumsq
// CSR by destination
__device__ int      g_deg[NMAX];
__device__ int      g_rowptr[NMAX + 1];
__device__ int      g_woff[NMAX];
__device__ int      g_csr_src[ETMAX];

// ---- helpers ----
__device__ __forceinline__ uint32_t h2u(__half2 h) {
    __half2_raw r = *reinterpret_cast<__half2_raw*>(&h);
    return (uint32_t)r.x | ((uint32_t)r.y << 16);
}
__device__ __forceinline__ float2 u2f2(uint32_t u) {
    __half2_raw r; r.x = (unsigned short)(u & 0xFFFFu); r.y = (unsigned short)(u >> 16);
    __half2 h = *reinterpret_cast<__half2*>(&r);
    return __half22float2(h);
}
__device__ __forceinline__ float lrelu(float v) { return v > 0.f ? v : 0.2f * v; }

__device__ __forceinline__ void cp16(uint32_t saddr, const void* gptr, bool pred) {
    int sz = pred ? 16 : 0;   // sz=0 -> 16 bytes zero-filled (src-size form)
    asm volatile("cp.async.cg.shared.global [%0], [%1], 16, %2;\n"
                 :: "r"(saddr), "l"(gptr), "r"(sz));
}
__device__ __forceinline__ void cp_commit() {
    asm volatile("cp.async.commit_group;\n" ::: "memory");
}
__device__ __forceinline__ void cp_waitg() {
    asm volatile("cp.async.wait_group %0;\n" :: "n"(GEMM_STAGES - 2) : "memory");
}
__device__ __forceinline__ void ldsm4(uint32_t* r, uint32_t addr) {
    asm volatile("ldmatrix.sync.aligned.m8n8.x4.shared.b16 {%0,%1,%2,%3}, [%4];"
                 : "=r"(r[0]), "=r"(r[1]), "=r"(r[2]), "=r"(r[3]) : "r"(addr));
}

// ---------------------------------------------------------------------------
// init: zero CSR degree + partial/final BN stats + attention accumulators
// ---------------------------------------------------------------------------
__global__ void k_init(int Nn) {
    int total = PSLOTS * 1024;               // 524288 >= Nn*4
    for (int i = blockIdx.x * blockDim.x + threadIdx.x; i < total;
         i += gridDim.x * blockDim.x) {
        g_pstats[i] = 0.f;
        if (i < Nn * 4) { g_asrc1[i] = 0.f; g_adst1[i] = 0.f; }
        if (i < Nn) g_deg[i] = 0;
        if (i < 1024) g_stats[i] = 0.f;
    }
}

// ---------------------------------------------------------------------------
// conversions: x -> fp16 ; W1 -> fp16 transposed [n][k]
// ---------------------------------------------------------------------------
__global__ void k_cvtA(const float* __restrict__ x, size_t n8) {
    const float4* src = (const float4*)x;
    uint4* dst = (uint4*)g_Ah;
    for (size_t i = (size_t)blockIdx.x * blockDim.x + threadIdx.x; i < n8;
         i += (size_t)gridDim.x * blockDim.x) {
        float4 v0 = __ldg(src + 2 * i);
        float4 v1 = __ldg(src + 2 * i + 1);
        uint4 o;
        o.x = h2u(__floats2half2_rn(v0.x, v0.y));
        o.y = h2u(__floats2half2_rn(v0.z, v0.w));
        o.z = h2u(__floats2half2_rn(v1.x, v1.y));
        o.w = h2u(__floats2half2_rn(v1.z, v1.w));
        dst[i] = o;
    }
}

__global__ void k_cvtBT(const float* __restrict__ W1) {
    __shared__ float t[32][33];
    int n0 = blockIdx.x * 32, k0 = blockIdx.y * 32;
    int tx = threadIdx.x, ty = threadIdx.y;   // 32 x 8
#pragma unroll
    for (int i = 0; i < 32; i += 8) {
        int k = k0 + ty + i;
        t[ty + i][tx] = (k < 2000) ? W1[(size_t)k * 2048 + n0 + tx] : 0.f;
    }
    __syncthreads();
#pragma unroll
    for (int i = 0; i < 32; i += 8) {
        int k = k0 + tx;
        if (k < 2000)
            g_W1h[(size_t)(n0 + ty + i) * 2000 + k] = __float2half_rn(t[tx][ty + i]);
    }
}

// ---------------------------------------------------------------------------
// CSR build: degree count -> exclusive scan -> scatter (src indices)
// ---------------------------------------------------------------------------
__global__ void k_deg(const int* __restrict__ ei, int E, int Nn) {
    int e = blockIdx.x * blockDim.x + threadIdx.x;
    if (e >= E + Nn) return;
    int d = (e < E) ? ei[E + e] : e - E;
    atomicAdd(&g_deg[d], 1);
}

__global__ void k_scan(int Nn) {
    __shared__ int wsum[32];
    __shared__ int carry_s;
    int tid = threadIdx.x;
    if (tid == 0) carry_s = 0;
    __syncthreads();
    int iters = (Nn + 1023) / 1024;
    for (int it = 0; it < iters; it++) {
        int i = it * 1024 + tid;
        int v = (i < Nn) ? g_deg[i] : 0;
        int x = v;
#pragma unroll
        for (int o = 1; o < 32; o <<= 1) {
            int y = __shfl_up_sync(0xffffffffu, x, o);
            if ((tid & 31) >= o) x += y;
        }
        if ((tid & 31) == 31) wsum[tid >> 5] = x;
        __syncthreads();
        if (tid < 32) {
            int w = wsum[tid];
#pragma unroll
            for (int o = 1; o < 32; o <<= 1) {
                int y = __shfl_up_sync(0xffffffffu, w, o);
                if (tid >= o) w += y;
            }
            wsum[tid] = w;
        }
        __syncthreads();
        int warp = tid >> 5;
        int incl = x + (warp ? wsum[warp - 1] : 0);
        int excl = incl - v;
        int c = carry_s;
        if (i < Nn) { g_rowptr[i] = c + excl; g_woff[i] = c + excl; }
        __syncthreads();
        if (tid == 1023) carry_s = c + incl;
        __syncthreads();
    }
    if (tid == 0) g_rowptr[Nn] = carry_s;
}

__global__ void k_scatter(const int* __restrict__ ei, int E, int Nn) {
    int e = blockIdx.x * blockDim.x + threadIdx.x;
    if (e >= E + Nn) return;
    int s, d;
    if (e < E) { s = ei[e]; d = ei[E + e]; } else { s = d = e - E; }
    int pos = atomicAdd(&g_woff[d], 1);
    g_csr_src[pos] = s;
}

// ---------------------------------------------------------------------------
// GEMM1 + fused attention dots: g_H1h = Ah @ W1h^T (fp16 mma, f32 accum,
// fp16 out). Epilogue computes per-(row,head) partial dots -> spread atomics.
// ---------------------------------------------------------------------------
__global__ __launch_bounds__(256, 2)
void k_gemm1h(const float* __restrict__ att_src, const float* __restrict__ att_dst,
              int M) {
    extern __shared__ char smem[];
    const uint32_t sb = (uint32_t)__cvta_generic_to_shared(smem);
    const __half* A = g_Ah;
    const __half* B = g_W1h;

    const int tid  = threadIdx.x;
    const int lane = tid & 31, warp = tid >> 5;
    const int gid  = lane >> 2, tig = lane & 3;
    const int wm   = warp >> 1, wn = warp & 1;
    const int rowBase = blockIdx.y * 128;
    const int colBase = blockIdx.x * 128;
    const int KITERS = 63;   // ceil(2000/32); tail chunks zero-filled by cp.async

    const int mrow = (lane & 7) + ((lane >> 3) & 1) * 8;
    const int koff = ((lane >> 4) & 1) * 16;

    float acc[2][8][4];
#pragma unroll
    for (int i = 0; i < 2; i++)
#pragma unroll
        for (int j = 0; j < 8; j++)
#pragma unroll
            for (int k = 0; k < 4; k++) acc[i][j][k] = 0.f;

    auto load_tile = [&](int st, int k0) {
        uint32_t aBase = sb + st * STAGE_BYTES;
        uint32_t bBase = aBase + OP_TILE;
#pragma unroll
        for (int i = 0; i < 2; i++) {
            int idx = tid + i * 256;
            int r = idx >> 2, j = idx & 3;
            int gr = rowBase + r;
            bool p = (gr < M) && (k0 + j * 8 < 2000);
            cp16(aBase + r * ROW_BYTES + j * 16, A + (size_t)gr * 2000 + k0 + j * 8, p);
        }
#pragma unroll
        for (int i = 0; i < 2; i++) {
            int idx = tid + i * 256;
            int r = idx >> 2, j = idx & 3;
            bool p = (k0 + j * 8 < 2000);
            cp16(bBase + r * ROW_BYTES + j * 16,
                 B + (size_t)(colBase + r) * 2000 + k0 + j * 8, p);
        }
    };

#pragma unroll
    for (int s = 0; s < GEMM_STAGES - 1; s++) {
        load_tile(s, s * 32);
        cp_commit();
    }

    for (int it = 0; it < KITERS; it++) {
        cp_waitg();
        __syncthreads();
        int st = it & (GEMM_STAGES - 1);
        uint32_t aBase = sb + st * STAGE_BYTES;
        uint32_t bBase = aBase + OP_TILE;
#pragma unroll
        for (int ks = 0; ks < 2; ks++) {
            uint32_t a[2][4], bf[4][4];
#pragma unroll
            for (int tm = 0; tm < 2; tm++) {
                uint32_t addr = aBase + (wm * 32 + tm * 16 + mrow) * ROW_BYTES
                              + ks * 32 + koff;
                ldsm4(a[tm], addr);
            }
#pragma unroll
            for (int tp = 0; tp < 4; tp++) {
                uint32_t addr = bBase + (wn * 64 + tp * 16 + mrow) * ROW_BYTES
                              + ks * 32 + koff;
                ldsm4(bf[tp], addr);
            }
#pragma unroll
            for (int tm = 0; tm < 2; tm++)
#pragma unroll
                for (int tp = 0; tp < 4; tp++) {
                    asm volatile(
                        "mma.sync.aligned.m16n8k16.row.col.f32.f16.f16.f32 "
                        "{%0,%1,%2,%3},{%4,%5,%6,%7},{%8,%9},{%0,%1,%2,%3};\n"
                        : "+f"(acc[tm][tp * 2][0]), "+f"(acc[tm][tp * 2][1]),
                          "+f"(acc[tm][tp * 2][2]), "+f"(acc[tm][tp * 2][3])
                        : "r"(a[tm][0]), "r"(a[tm][1]), "r"(a[tm][2]), "r"(a[tm][3]),
                          "r"(bf[tp][0]), "r"(bf[tp][2]));
                    asm volatile(
                        "mma.sync.aligned.m16n8k16.row.col.f32.f16.f16.f32 "
                        "{%0,%1,%2,%3},{%4,%5,%6,%7},{%8,%9},{%0,%1,%2,%3};\n"
                        : "+f"(acc[tm][tp * 2 + 1][0]), "+f"(acc[tm][tp * 2 + 1][1]),
                          "+f"(acc[tm][tp * 2 + 1][2]), "+f"(acc[tm][tp * 2 + 1][3])
                        : "r"(a[tm][0]), "r"(a[tm][1]), "r"(a[tm][2]), "r"(a[tm][3]),
                          "r"(bf[tp][1]), "r"(bf[tp][3]));
                }
        }
        int nit = it + GEMM_STAGES - 1;
        if (nit < KITERS) load_tile(nit & (GEMM_STAGES - 1), nit * 32);
        cp_commit();
    }

    // ---- epilogue: fp16 H1 store + fused attention partial dots ----
    const int hIdx = colBase >> 9;                      // single head per CTA
    const int cgBase = (colBase & 511) + wn * 64 + tig * 2;
    const float* asv = att_src + hIdx * 512;
    const float* adv = att_dst + hIdx * 512;

    float psrc[4] = {0.f, 0.f, 0.f, 0.f};               // [tm*2 + half]
    float pdst[4] = {0.f, 0.f, 0.f, 0.f};

#pragma unroll
    for (int tm = 0; tm < 2; tm++) {
        int r0 = rowBase + wm * 32 + tm * 16 + gid;
#pragma unroll
        for (int tn = 0; tn < 8; tn++) {
            int c = colBase + wn * 64 + tn * 8 + tig * 2;
            uint32_t p01 = h2u(__floats2half2_rn(acc[tm][tn][0], acc[tm][tn][1]));
            uint32_t p23 = h2u(__floats2half2_rn(acc[tm][tn][2], acc[tm][tn][3]));
            if (r0 < M)
                *(uint32_t*)(g_H1h + (size_t)r0 * 2048 + c) = p01;
            if (r0 + 8 < M)
                *(uint32_t*)(g_H1h + (size_t)(r0 + 8) * 2048 + c) = p23;

            float2 av = __ldg((const float2*)(asv + cgBase + tn * 8));
            float2 dv = __ldg((const float2*)(adv + cgBase + tn * 8));
            psrc[tm * 2 + 0] += acc[tm][tn][0] * av.x + acc[tm][tn][1] * av.y;
            psrc[tm * 2 + 1] += acc[tm][tn][2] * av.x + acc[tm][tn][3] * av.y;
            pdst[tm * 2 + 0] += acc[tm][tn][0] * dv.x + acc[tm][tn][1] * dv.y;
            pdst[tm * 2 + 1] += acc[tm][tn][2] * dv.x + acc[tm][tn][3] * dv.y;
        }
    }
#pragma unroll
    for (int tm = 0; tm < 2; tm++)
#pragma unroll
        for (int half = 0; half < 2; half++) {
            int row = rowBase + wm * 32 + tm * 16 + half * 8 + gid;
            if (row < M) {
                atomicAdd(g_asrc1 + row * 4 + hIdx, psrc[tm * 2 + half]);
                atomicAdd(g_adst1 + row * 4 + hIdx, pdst[tm * 2 + half]);
            }
        }
}

// ---------------------------------------------------------------------------
// fused layer-1 softmax + aggregation + hashed BN-stat partials:
// one block (256 thr) per destination.
// ---------------------------------------------------------------------------
__global__ __launch_bounds__(256)
void k_agg1(int Nn) {
    const int d = blockIdx.x;
    const int tid = threadIdx.x, lane = tid & 31, warp = tid >> 5;
    const int beg = g_rowptr[d], end = g_rowptr[d + 1];

    __shared__ float4 rwarp[8];
    __shared__ float4 rbc;
    __shared__ int    ssrc[256];
    __shared__ float4 sal[256];

    float4 ad = *(const float4*)(g_adst1 + (size_t)d * 4);
    const float NEGINF = __int_as_float(0xff800000);

    float4 mx = make_float4(NEGINF, NEGINF, NEGINF, NEGINF);
    for (int j = beg + tid; j < end; j += 256) {
        int s = g_csr_src[j];
        float4 as = *(const float4*)(g_asrc1 + (size_t)s * 4);
        mx.x = fmaxf(mx.x, lrelu(as.x + ad.x));
        mx.y = fmaxf(mx.y, lrelu(as.y + ad.y));
        mx.z = fmaxf(mx.z, lrelu(as.z + ad.z));
        mx.w = fmaxf(mx.w, lrelu(as.w + ad.w));
    }
#pragma unroll
    for (int o = 16; o; o >>= 1) {
        mx.x = fmaxf(mx.x, __shfl_down_sync(0xffffffffu, mx.x, o));
        mx.y = fmaxf(mx.y, __shfl_down_sync(0xffffffffu, mx.y, o));
        mx.z = fmaxf(mx.z, __shfl_down_sync(0xffffffffu, mx.z, o));
        mx.w = fmaxf(mx.w, __shfl_down_sync(0xffffffffu, mx.w, o));
    }
    if (lane == 0) rwarp[warp] = mx;
    __syncthreads();
    if (tid == 0) {
        float4 m = rwarp[0];
#pragma unroll
        for (int w = 1; w < 8; w++) {
            m.x = fmaxf(m.x, rwarp[w].x); m.y = fmaxf(m.y, rwarp[w].y);
            m.z = fmaxf(m.z, rwarp[w].z); m.w = fmaxf(m.w, rwarp[w].w);
        }
        rbc = m;
    }
    __syncthreads();
    mx = rbc;

    float4 sm = make_float4(0.f, 0.f, 0.f, 0.f);
    for (int j = beg + tid; j < end; j += 256) {
        int s = g_csr_src[j];
        float4 as = *(const float4*)(g_asrc1 + (size_t)s * 4);
        sm.x += expf(lrelu(as.x + ad.x) - mx.x);
        sm.y += expf(lrelu(as.y + ad.y) - mx.y);
        sm.z += expf(lrelu(as.z + ad.z) - mx.z);
        sm.w += expf(lrelu(as.w + ad.w) - mx.w);
    }
#pragma unroll
    for (int o = 16; o; o >>= 1) {
        sm.x += __shfl_down_sync(0xffffffffu, sm.x, o);
        sm.y += __shfl_down_sync(0xffffffffu, sm.y, o);
        sm.z += __shfl_down_sync(0xffffffffu, sm.z, o);
        sm.w += __shfl_down_sync(0xffffffffu, sm.w, o);
    }
    if (lane == 0) rwarp[warp] = sm;
    __syncthreads();
    if (tid == 0) {
        float4 t = rwarp[0];
#pragma unroll
        for (int w = 1; w < 8; w++) {
            t.x += rwarp[w].x; t.y += rwarp[w].y; t.z += rwarp[w].z; t.w += rwarp[w].w;
        }
        rbc = t;
    }
    __syncthreads();
    sm = rbc;
    float4 inv;
    inv.x = 0.25f / (sm.x + 1e-16f);
    inv.y = 0.25f / (sm.y + 1e-16f);
    inv.z = 0.25f / (sm.z + 1e-16f);
    inv.w = 0.25f / (sm.w + 1e-16f);

    float2 acc = make_float2(0.f, 0.f);
    for (int c0 = beg; c0 < end; c0 += 256) {
        int cnt = min(end - c0, 256);
        __syncthreads();
        if (tid < cnt) {
            int s = g_csr_src[c0 + tid];
            float4 as = *(const float4*)(g_asrc1 + (size_t)s * 4);
            float4 al;
            al.x = expf(lrelu(as.x + ad.x) - mx.x) * inv.x;
            al.y = expf(lrelu(as.y + ad.y) - mx.y) * inv.y;
            al.z = expf(lrelu(as.z + ad.z) - mx.z) * inv.z;
            al.w = expf(lrelu(as.w + ad.w) - mx.w) * inv.w;
            ssrc[tid] = s;
            sal[tid] = al;
        }
        __syncthreads();
        for (int jj = 0; jj < cnt; jj++) {
            const __half* h = g_H1h + (size_t)ssrc[jj] * 2048 + 2 * tid;
            float4 al = sal[jj];
            float2 v0 = u2f2(__ldg((const uint32_t*)(h)));
            float2 v1 = u2f2(__ldg((const uint32_t*)(h + 512)));
            float2 v2 = u2f2(__ldg((const uint32_t*)(h + 1024)));
            float2 v3 = u2f2(__ldg((const uint32_t*)(h + 1536)));
            acc.x += al.x * v0.x + al.y * v1.x + al.z * v2.x + al.w * v3.x;
            acc.y += al.x * v0.y + al.y * v1.y + al.z * v2.y + al.w * v3.y;
        }
    }
    *(float2*)(g_out1 + (size_t)d * 512 + 2 * tid) = acc;

    // hashed BN-stat partials: slot = d & 511 -> ~49 atomics per address
    float* ps = g_pstats + (size_t)(d & (PSLOTS - 1)) * 1024;
    atomicAdd(ps + 2 * tid,           acc.x);
    atomicAdd(ps + 2 * tid + 1,       acc.y);
    atomicAdd(ps + 512 + 2 * tid,     acc.x * acc.x);
    atomicAdd(ps + 512 + 2 * tid + 1, acc.y * acc.y);
}

// ---------------------------------------------------------------------------
// reduce hashed partials -> g_stats (2 MB, L2-resident)
// ---------------------------------------------------------------------------
__global__ void k_statsred() {
    int i = blockIdx.x * blockDim.x + threadIdx.x;   // 0..1023
    if (i >= 1024) return;
    float s = 0.f;
#pragma unroll 8
    for (int r = 0; r < PSLOTS; r++)
        s += g_pstats[(size_t)r * 1024 + i];
    g_stats[i] = s;
}

// ---------------------------------------------------------------------------
// layer-2 prep with fused BN+ELU: H2 = ELU(BN(out1)) @ W2 (one warp per row)
// ---------------------------------------------------------------------------
__global__ void k_l2prep(const float* __restrict__ W2, const float* __restrict__ as2,
                         const float* __restrict__ ad2, const float* __restrict__ gamma,
                         const float* __restrict__ beta, int Nn, float invN) {
    int gw = (int)(((size_t)blockIdx.x * blockDim.x + threadIdx.x) >> 5);
    int lane = threadIdx.x & 31;
    if (gw >= Nn) return;
    const float* h = g_out1 + (size_t)gw * 512;
    float acc = 0.f;
    for (int kb = 0; kb < 16; kb++) {
        int c = kb * 32 + lane;
        float mu = __ldg(g_stats + c) * invN;
        float var = __ldg(g_stats + 512 + c) * invN - mu * mu;
        float scale = rsqrtf(var + 1e-5f) * __ldg(gamma + c);
        float shift = __ldg(beta + c) - mu * scale;
        float xv = h[c] * scale + shift;
        float hv = xv > 0.f ? xv : expm1f(xv);
#pragma unroll
        for (int j = 0; j < 32; j++) {
            float hk = __shfl_sync(0xffffffffu, hv, j);
            float w = (lane < 30) ? __ldg(W2 + (size_t)(kb * 32 + j) * 30 + lane) : 0.f;
            acc = fmaf(hk, w, acc);
        }
    }
    float sa = (lane < 30) ? acc * __ldg(as2 + lane) : 0.f;
    float sd = (lane < 30) ? acc * __ldg(ad2 + lane) : 0.f;
#pragma unroll
    for (int off = 16; off; off >>= 1) {
        sa += __shfl_down_sync(0xffffffffu, sa, off);
        sd += __shfl_down_sync(0xffffffffu, sd, off);
    }
    if (lane < 30) g_H2[(size_t)gw * 30 + lane] = acc;
    if (lane == 0) { g_asrc2[gw] = sa; g_adst2[gw] = sd; }
}

// ---------------------------------------------------------------------------
// fused layer-2 softmax + aggregation: one warp per destination.
// ---------------------------------------------------------------------------
__global__ __launch_bounds__(256)
void k_l2agg(const float* __restrict__ b2, float* __restrict__ out, int Nn) {
    int gw = (int)(((size_t)blockIdx.x * blockDim.x + threadIdx.x) >> 5);
    int lane = threadIdx.x & 31;
    if (gw >= Nn) return;
    const int d = gw;
    const int beg = g_rowptr[d], end = g_rowptr[d + 1];
    const float adv = g_adst2[d];
    const float NEGINF = __int_as_float(0xff800000);

    float mx = NEGINF;
    for (int j = beg + lane; j < end; j += 32)
        mx = fmaxf(mx, lrelu(__ldg(g_asrc2 + g_csr_src[j]) + adv));
#pragma unroll
    for (int o = 16; o; o >>= 1)
        mx = fmaxf(mx, __shfl_xor_sync(0xffffffffu, mx, o));

    float sm = 0.f;
    for (int j = beg + lane; j < end; j += 32)
        sm += expf(lrelu(__ldg(g_asrc2 + g_csr_src[j]) + adv) - mx);
#pragma unroll
    for (int o = 16; o; o >>= 1)
        sm += __shfl_xor_sync(0xffffffffu, sm, o);
    float inv = 1.f / (sm + 1e-16f);

    float acc = 0.f;
    for (int j = beg; j < end; j++) {
        int s = g_csr_src[j];
        float al = expf(lrelu(__ldg(g_asrc2 + s) + adv) - mx) * inv;
        if (lane < 30) acc = fmaf(al, __ldg(g_H2 + (size_t)s * 30 + lane), acc);
    }
    if (lane < 30) out[(size_t)d * 30 + lane] = acc + __ldg(b2 + lane);
}

// ---------------------------------------------------------------------------
// launch: fork CSR branch (deg/scan/scatter) parallel to cvt+GEMM branch
// ---------------------------------------------------------------------------
extern "C" void kernel_launch(void* const* d_in, const int* in_sizes, int n_in,
                              void* d_out, int out_size) {
    const float* x       = (const float*)d_in[0];
    const int*   ei      = (const int*)d_in[1];
    const float* W1      = (const float*)d_in[2];
    const float* attsrc1 = (const float*)d_in[3];
    const float* attdst1 = (const float*)d_in[4];
    // d_in[5] = b1: BN-invariant, skipped
    const float* gamma   = (const float*)d_in[6];
    const float* beta    = (const float*)d_in[7];
    const float* W2      = (const float*)d_in[8];
    const float* attsrc2 = (const float*)d_in[9];
    const float* attdst2 = (const float*)d_in[10];
    const float* b2      = (const float*)d_in[11];
    float* out = (float*)d_out;

    int Nn = in_sizes[0] / 2000;
    int E  = in_sizes[1] / 2;
    int Etot = E + Nn;
    int eb = (Etot + 255) / 256;

    cudaFuncSetAttribute(k_gemm1h, cudaFuncAttributeMaxDynamicSharedMemorySize, SMEM_GEMM);

    cudaStream_t s2;
    cudaEvent_t evFork, evJoin;
    cudaStreamCreateWithFlags(&s2, cudaStreamNonBlocking);
    cudaEventCreateWithFlags(&evFork, cudaEventDisableTiming);
    cudaEventCreateWithFlags(&evJoin, cudaEventDisableTiming);

    k_init<<<512, 256>>>(Nn);

    // fork: CSR branch on s2
    cudaEventRecord(evFork, 0);
    cudaStreamWaitEvent(s2, evFork, 0);
    k_deg<<<eb, 256, 0, s2>>>(ei, E, Nn);
    k_scan<<<1, 1024, 0, s2>>>(Nn);
    k_scatter<<<eb, 256, 0, s2>>>(ei, E, Nn);
    cudaEventRecord(evJoin, s2);

    // main branch: conversions + GEMM(+att dots)
    k_cvtA<<<2048, 256>>>(x, (size_t)Nn * 2000 / 8);
    k_cvtBT<<<dim3(64, 63), dim3(32, 8)>>>(W1);
    dim3 g1(16, (Nn + 127) / 128);
    k_gemm1h<<<g1, 256, SMEM_GEMM>>>(attsrc1, attdst1, Nn);

    // join: agg1 needs CSR + attention scalars
    cudaStreamWaitEvent(0, evJoin, 0);
    k_agg1<<<Nn, 256>>>(Nn);

    k_statsred<<<4, 256>>>();

    k_l2prep<<<(int)(((size_t)Nn * 32 + 255) / 256), 256>>>(
        W2, attsrc2, attdst2, gamma, beta, Nn, 1.f / (float)Nn);

    k_l2agg<<<(int)(((size_t)Nn * 32 + 255) / 256), 256>>>(b2, out, Nn);
}